// round 5
// baseline (speedup 1.0000x reference)
#include <cuda_runtime.h>
#include <cuda_bf16.h>
#include <cstdint>

// ---------------- problem constants ----------------
#define BB     4
#define CC     64
#define H0     48
#define W0     48
#define QQ     16384
#define MROWS  (BB*QQ*4)     // 262144
#define HID    256
#define K0PAD  320           // layer-0 K (260) padded to multiple of 16

// ---------------- scratch ----------------
__device__ float g_feat [BB*CC*H0*W0];
__device__ float g_feat1[BB*CC*96*96];
__device__ float g_feat2[BB*CC*192*192];
__device__ float g_feat3[BB*CC*384*384];
__device__ float g_feat4[BB*CC*192*192];
__device__ float g_feat5[BB*CC*96*96];
__device__ __nv_bfloat16 g_Xhi[(size_t)MROWS*K0PAD];
__device__ __nv_bfloat16 g_Xlo[(size_t)MROWS*K0PAD];
__device__ __nv_bfloat16 g_HAhi[(size_t)MROWS*HID];
__device__ __nv_bfloat16 g_HAlo[(size_t)MROWS*HID];
__device__ __nv_bfloat16 g_HBhi[(size_t)MROWS*HID];
__device__ __nv_bfloat16 g_HBlo[(size_t)MROWS*HID];
__device__ __nv_bfloat16 g_Wthi[256*K0PAD + 3*256*256];
__device__ __nv_bfloat16 g_Wtlo[256*K0PAD + 3*256*256];
__device__ float g_P   [(size_t)MROWS*3];
__device__ float g_area[MROWS];

__device__ __forceinline__ uint32_t smem_u32(const void* p) {
    uint32_t a;
    asm("{ .reg .u64 t; cvta.to.shared.u64 t, %1; cvt.u32.u64 %0, t; }" : "=r"(a) : "l"(p));
    return a;
}
__device__ __forceinline__ void cp16(uint32_t dst, const void* src) {
    asm volatile("cp.async.cg.shared.global [%0], [%1], 16;" :: "r"(dst), "l"(src));
}
__device__ __forceinline__ void split_bf16(float v, __nv_bfloat16& hi, __nv_bfloat16& lo)
{
    hi = __float2bfloat16(v);
    lo = __float2bfloat16(v - __bfloat162float(hi));
}

// ================= conv kernels (unchanged, passing) =================
__global__ void enc_conv(const float* __restrict__ inp,
                         const float* __restrict__ w,
                         const float* __restrict__ b)
{
    int idx = blockIdx.x*256 + threadIdx.x;
    if (idx >= BB*CC*H0*W0) return;
    int x  = idx % W0;
    int y  = (idx / W0) % H0;
    int co = (idx / (H0*W0)) % CC;
    int bb = idx / (H0*W0*CC);
    float acc = b[co];
    const float* ib = inp + (size_t)bb*3*H0*W0;
    #pragma unroll
    for (int ci = 0; ci < 3; ci++) {
        #pragma unroll
        for (int ky = 0; ky < 3; ky++) {
            int yy = y + ky - 1;
            if (yy < 0 || yy >= H0) continue;
            #pragma unroll
            for (int kx = 0; kx < 3; kx++) {
                int xx = x + kx - 1;
                if (xx < 0 || xx >= W0) continue;
                acc += ib[ci*H0*W0 + yy*W0 + xx] * w[(co*3 + ci)*9 + ky*3 + kx];
            }
        }
    }
    g_feat[idx] = acc;
}

__global__ void up_conv_ps(const float* __restrict__ in, float* __restrict__ out,
                           int H, int W,
                           const float* __restrict__ w, const float* __restrict__ bias)
{
    __shared__ float s_in[8][18][18];
    __shared__ float s_w[4][8][9];
    int tx = threadIdx.x, ty = threadIdx.y, tid = ty*16 + tx;
    int x0 = blockIdx.x*16, y0 = blockIdx.y*16;
    int bb = blockIdx.z >> 6;
    int cog = blockIdx.z & 63;
    float acc[4] = {0.f,0.f,0.f,0.f};
    const float* inb = in + (size_t)bb*CC*H*W;

    for (int c0 = 0; c0 < CC; c0 += 8) {
        for (int i = tid; i < 8*18*18; i += 256) {
            int ci = i / 324, rem = i % 324, r = rem / 18, c = rem % 18;
            int y = y0 + r - 1, x = x0 + c - 1;
            float v = 0.f;
            if (y >= 0 && y < H && x >= 0 && x < W)
                v = inb[(size_t)(c0+ci)*H*W + y*W + x];
            s_in[ci][r][c] = v;
        }
        for (int i = tid; i < 288; i += 256) {
            int col = i / 72, rem = i % 72, ci = rem / 9, k = rem % 9;
            s_w[col][ci][k] = w[((size_t)(cog*4+col)*CC + c0+ci)*9 + k];
        }
        __syncthreads();
        #pragma unroll
        for (int ci = 0; ci < 8; ci++) {
            float v[9];
            #pragma unroll
            for (int j = 0; j < 9; j++) v[j] = s_in[ci][ty + j/3][tx + j%3];
            #pragma unroll
            for (int col = 0; col < 4; col++) {
                float a = acc[col];
                #pragma unroll
                for (int k = 0; k < 9; k++) a += v[k]*s_w[col][ci][k];
                acc[col] = a;
            }
        }
        __syncthreads();
    }
    int H2 = 2*H, W2 = 2*W;
    float* ob = out + ((size_t)bb*CC + cog)*H2*W2;
    int oy = y0 + ty, ox = x0 + tx;
    #pragma unroll
    for (int col = 0; col < 4; col++) {
        int r = col >> 1, s = col & 1;
        ob[(size_t)(2*oy + r)*W2 + 2*ox + s] = acc[col] + bias[cog*4 + col];
    }
}

__global__ void down_fused(const float* __restrict__ in3, const float* __restrict__ skin,
                           float* __restrict__ out, int OH, int OW,
                           const float* __restrict__ dw, const float* __restrict__ db,
                           const float* __restrict__ sw, const float* __restrict__ sb)
{
    __shared__ float s_in[8][33][33];
    __shared__ float s_w[4][8][9];
    __shared__ float s_sw[4][8];
    int IH = 2*OH, IW = 2*OW;
    int tx = threadIdx.x, ty = threadIdx.y, tid = ty*16 + tx;
    int x0 = blockIdx.x*16, y0 = blockIdx.y*16;
    int bb = blockIdx.z >> 4;
    int cog = blockIdx.z & 15;
    float acc[4] = {0.f,0.f,0.f,0.f};
    const float* inb = in3 + (size_t)bb*CC*IH*IW;
    const float* skb = skin + (size_t)bb*CC*OH*OW;
    int oy = y0 + ty, ox = x0 + tx;

    for (int c0 = 0; c0 < CC; c0 += 8) {
        for (int i = tid; i < 8*33*33; i += 256) {
            int ci = i / 1089, rem = i % 1089, r = rem / 33, c = rem % 33;
            int y = 2*y0 - 1 + r, x = 2*x0 - 1 + c;
            float v = 0.f;
            if (y >= 0 && y < IH && x >= 0 && x < IW)
                v = inb[(size_t)(c0+ci)*IH*IW + y*IW + x];
            s_in[ci][r][c] = v;
        }
        for (int i = tid; i < 288; i += 256) {
            int col = i / 72, rem = i % 72, ci = rem / 9, k = rem % 9;
            s_w[col][ci][k] = dw[((size_t)(cog*4+col)*CC + c0+ci)*9 + k];
        }
        if (tid < 32) {
            int col = tid >> 3, ci = tid & 7;
            s_sw[col][ci] = sw[(cog*4+col)*CC + c0+ci];
        }
        __syncthreads();
        #pragma unroll
        for (int ci = 0; ci < 8; ci++) {
            float v[9];
            #pragma unroll
            for (int j = 0; j < 9; j++) v[j] = s_in[ci][2*ty + j/3][2*tx + j%3];
            float sv = skb[(size_t)(c0+ci)*OH*OW + oy*OW + ox];
            #pragma unroll
            for (int col = 0; col < 4; col++) {
                float a = acc[col];
                #pragma unroll
                for (int k = 0; k < 9; k++) a += v[k]*s_w[col][ci][k];
                a += sv * s_sw[col][ci];
                acc[col] = a;
            }
        }
        __syncthreads();
    }
    float* ob = out + (size_t)bb*CC*OH*OW;
    #pragma unroll
    for (int col = 0; col < 4; col++) {
        int co = cog*4 + col;
        ob[(size_t)co*OH*OW + oy*OW + ox] = acc[col] + db[co] + sb[co];
    }
}

// ================= weight prep: transpose + bf16 hi/lo split =================
// layout: L0 at 0 (256 x 320), L1/L2/L3 at 81920 + l*65536 (256 x 256), row n, col k
__global__ void prep_w(const float* __restrict__ w0, const float* __restrict__ w1,
                       const float* __restrict__ w2, const float* __restrict__ w3)
{
    int i = blockIdx.x*256 + threadIdx.x;
    int total = 256*K0PAD + 3*256*256;
    if (i >= total) return;
    float v;
    if (i < 256*K0PAD) {
        int n = i / K0PAD, k = i % K0PAD;
        v = (k < 260) ? w0[(size_t)k*256 + n] : 0.0f;
    } else {
        int j = i - 256*K0PAD;
        int l = j / 65536, r = j % 65536;
        int n = r / 256, k = r % 256;
        const float* ws = (l == 0) ? w1 : (l == 1) ? w2 : w3;
        v = ws[(size_t)k*256 + n];
    }
    __nv_bfloat16 hi, lo;
    split_bf16(v, hi, lo);
    g_Wthi[i] = hi;
    g_Wtlo[i] = lo;
}

// ================= gather + build X (bf16 hi/lo, K0PAD cols) =================
__device__ __forceinline__ int nidx(float cc, float n)
{
    float f = rintf((cc + 1.0f)*(n*0.5f) - 0.5f);
    f = fminf(fmaxf(f, 0.0f), n - 1.0f);
    return (int)f;
}

__global__ void gather_build(const float* __restrict__ coord, const float* __restrict__ cell)
{
    int tid = threadIdx.x;
    int row = blockIdx.x*4 + (tid >> 6);
    int c   = tid & 63;
    int s   = row & 3;
    int bq  = row >> 2;
    int b   = bq >> 14;
    float cy = coord[(size_t)bq*2 + 0];
    float cx = coord[(size_t)bq*2 + 1];
    float vx = (s & 2) ? 1.f : -1.f;
    float vy = (s & 1) ? 1.f : -1.f;
    const float RX = 1.0f/48.0f;
    float sy = fminf(fmaxf(cy + vx*RX + 1e-6f, -1.f + 1e-6f), 1.f - 1e-6f);
    float sx = fminf(fmaxf(cx + vy*RX + 1e-6f, -1.f + 1e-6f), 1.f - 1e-6f);
    int iy0 = nidx(sy, 48.f),  ix0 = nidx(sx, 48.f);
    int iy1 = nidx(sy, 96.f),  ix1 = nidx(sx, 96.f);
    int iy2 = nidx(sy, 192.f), ix2 = nidx(sx, 192.f);
    int iy3 = nidx(sy, 384.f), ix3 = nidx(sx, 384.f);

    __nv_bfloat16* xh = g_Xhi + (size_t)row*K0PAD;
    __nv_bfloat16* xl = g_Xlo + (size_t)row*K0PAD;

    float f0 = g_feat [((size_t)(b*CC + c)*48  + iy0)*48  + ix0];
    float f5 = g_feat5[((size_t)(b*CC + c)*96  + iy1)*96  + ix1];
    float f4 = g_feat4[((size_t)(b*CC + c)*192 + iy2)*192 + ix2];
    float f3 = g_feat3[((size_t)(b*CC + c)*384 + iy3)*384 + ix3];
    __nv_bfloat16 hi, lo;
    split_bf16(f0, hi, lo); xh[c]       = hi; xl[c]       = lo;
    split_bf16(f5, hi, lo); xh[64 + c]  = hi; xl[64 + c]  = lo;
    split_bf16(f4, hi, lo); xh[128 + c] = hi; xl[128 + c] = lo;
    split_bf16(f3, hi, lo); xh[192 + c] = hi; xl[192 + c] = lo;

    if (c == 0) {
        float qcy = -1.f + (2.f*iy0 + 1.f)/48.f;
        float qcx = -1.f + (2.f*ix0 + 1.f)/48.f;
        float ry_ = (cy - qcy)*48.f;
        float rx_ = (cx - qcx)*48.f;
        split_bf16(ry_, hi, lo); xh[256] = hi; xl[256] = lo;
        split_bf16(rx_, hi, lo); xh[257] = hi; xl[257] = lo;
        split_bf16(cell[(size_t)bq*2 + 0]*48.f, hi, lo); xh[258] = hi; xl[258] = lo;
        split_bf16(cell[(size_t)bq*2 + 1]*48.f, hi, lo); xh[259] = hi; xl[259] = lo;
        g_area[row] = fabsf(ry_*rx_) + 1e-9f;
    }
    if (c < 60) {
        __nv_bfloat16 z = __float2bfloat16(0.0f);
        xh[260 + c] = z; xl[260 + c] = z;
    }
}

// ================= bf16 mma.sync GEMM (base-arch tensor cores) =================
// C[M,256] = relu(A@W + bias); A = Ahi+Alo (row-major, stride K), W as Wt[n][k] hi/lo.
// 3-pass split: Ahi*Whi + Ahi*Wlo + Alo*Whi, fp32 accum.
// CTA tile 128x128, 8 warps (warp tile 32x64), BK=16, 2-stage cp.async pipeline.
#define LDS_ROW 24   // padded smem row length (bf16 elems) = 48 bytes

__global__ void __launch_bounds__(256)
mlp_gemm_mma(const __nv_bfloat16* __restrict__ Ahi, const __nv_bfloat16* __restrict__ Alo,
             int K,
             const __nv_bfloat16* __restrict__ Whi, const __nv_bfloat16* __restrict__ Wlo,
             const float* __restrict__ bias,
             __nv_bfloat16* __restrict__ Ohi, __nv_bfloat16* __restrict__ Olo)
{
    __shared__ __nv_bfloat16 sA[2][128*LDS_ROW];
    __shared__ __nv_bfloat16 sB[2][128*LDS_ROW];
    int tid = threadIdx.x, lane = tid & 31, wid = tid >> 5;
    int m0 = blockIdx.x*128, n0 = blockIdx.y*128;
    int wm = (wid & 3)*32, wn = (wid >> 2)*64;
    int KS = K >> 4, total = 3*KS;

    uint32_t sAb = smem_u32(&sA[0][0]);
    uint32_t sBb = smem_u32(&sB[0][0]);
    const uint32_t STG = 128*LDS_ROW*2;   // stage stride bytes

    float c[2][8][4];
    #pragma unroll
    for (int mi = 0; mi < 2; mi++)
        #pragma unroll
        for (int ni = 0; ni < 8; ni++)
            #pragma unroll
            for (int j = 0; j < 4; j++) c[mi][ni][j] = 0.f;

    int lrow = tid >> 1, lhalf = tid & 1;
    uint32_t sdst_off = (uint32_t)(lrow*LDS_ROW + lhalf*8)*2;

    // stage loader
    auto issue = [&](int it, int st) {
        int pass = it / KS, kk = it - pass*KS;
        const __nv_bfloat16* Asrc = (pass == 2) ? Alo : Ahi;
        const __nv_bfloat16* Wsrc = (pass == 1) ? Wlo : Whi;
        int k0 = kk << 4;
        cp16(sAb + st*STG + sdst_off, Asrc + (size_t)(m0 + lrow)*K + k0 + lhalf*8);
        cp16(sBb + st*STG + sdst_off, Wsrc + (size_t)(n0 + lrow)*K + k0 + lhalf*8);
        asm volatile("cp.async.commit_group;");
    };

    issue(0, 0);

    for (int it = 0; it < total; it++) {
        int st = it & 1;
        if (it + 1 < total) {
            issue(it + 1, (it + 1) & 1);
            asm volatile("cp.async.wait_group 1;");
        } else {
            asm volatile("cp.async.wait_group 0;");
        }
        __syncthreads();

        // ---- compute on stage st ----
        uint32_t af[2][4];
        #pragma unroll
        for (int mi = 0; mi < 2; mi++) {
            uint32_t addr = sAb + st*STG +
                (uint32_t)((wm + mi*16 + (lane & 15))*LDS_ROW + (lane >> 4)*8)*2;
            asm volatile("ldmatrix.sync.aligned.m8n8.x4.shared.b16 {%0,%1,%2,%3}, [%4];"
                : "=r"(af[mi][0]), "=r"(af[mi][1]), "=r"(af[mi][2]), "=r"(af[mi][3])
                : "r"(addr));
        }
        uint32_t bf[8][2];
        #pragma unroll
        for (int ni = 0; ni < 8; ni++) {
            uint32_t addr = sBb + st*STG +
                (uint32_t)((wn + ni*8 + (lane & 7))*LDS_ROW + ((lane >> 3) & 1)*8)*2;
            asm volatile("ldmatrix.sync.aligned.m8n8.x2.shared.b16 {%0,%1}, [%2];"
                : "=r"(bf[ni][0]), "=r"(bf[ni][1]) : "r"(addr));
        }
        #pragma unroll
        for (int mi = 0; mi < 2; mi++)
            #pragma unroll
            for (int ni = 0; ni < 8; ni++) {
                asm volatile(
                    "mma.sync.aligned.m16n8k16.row.col.f32.bf16.bf16.f32 "
                    "{%0,%1,%2,%3}, {%4,%5,%6,%7}, {%8,%9}, {%0,%1,%2,%3};"
                    : "+f"(c[mi][ni][0]), "+f"(c[mi][ni][1]),
                      "+f"(c[mi][ni][2]), "+f"(c[mi][ni][3])
                    : "r"(af[mi][0]), "r"(af[mi][1]), "r"(af[mi][2]), "r"(af[mi][3]),
                      "r"(bf[ni][0]), "r"(bf[ni][1]));
            }
        __syncthreads();
    }

    // ---- epilogue: bias + relu + hi/lo split ----
    #pragma unroll
    for (int mi = 0; mi < 2; mi++) {
        int r0 = m0 + wm + mi*16 + (lane >> 2);
        #pragma unroll
        for (int ni = 0; ni < 8; ni++) {
            int ncol = n0 + wn + ni*8 + 2*(lane & 3);
            float b0 = bias[ncol], b1 = bias[ncol + 1];
            #pragma unroll
            for (int half = 0; half < 2; half++) {
                int r = r0 + half*8;
                float v0 = fmaxf(c[mi][ni][2*half + 0] + b0, 0.f);
                float v1 = fmaxf(c[mi][ni][2*half + 1] + b1, 0.f);
                __nv_bfloat16 h0, l0, h1, l1;
                split_bf16(v0, h0, l0);
                split_bf16(v1, h1, l1);
                uint32_t hp = ((uint32_t)__bfloat16_as_ushort(h1) << 16) |
                              (uint32_t)__bfloat16_as_ushort(h0);
                uint32_t lp = ((uint32_t)__bfloat16_as_ushort(l1) << 16) |
                              (uint32_t)__bfloat16_as_ushort(l0);
                *(uint32_t*)(Ohi + (size_t)r*HID + ncol) = hp;
                *(uint32_t*)(Olo + (size_t)r*HID + ncol) = lp;
            }
        }
    }
}

// ================= last layer: [M,256]@[256,3]+b (hi/lo input) =================
__global__ void mlp_last(const __nv_bfloat16* __restrict__ Hhi, const __nv_bfloat16* __restrict__ Hlo,
                         const float* __restrict__ W4, const float* __restrict__ b4)
{
    int warp = threadIdx.x >> 5, lane = threadIdx.x & 31;
    int row = blockIdx.x*4 + warp;
    const __nv_bfloat16* hh = Hhi + (size_t)row*HID;
    const __nv_bfloat16* hl = Hlo + (size_t)row*HID;
    float a0 = 0.f, a1 = 0.f, a2 = 0.f;
    for (int k = lane; k < HID; k += 32) {
        float h = __bfloat162float(hh[k]) + __bfloat162float(hl[k]);
        a0 += h*W4[k*3 + 0];
        a1 += h*W4[k*3 + 1];
        a2 += h*W4[k*3 + 2];
    }
    #pragma unroll
    for (int o = 16; o; o >>= 1) {
        a0 += __shfl_down_sync(0xffffffffu, a0, o);
        a1 += __shfl_down_sync(0xffffffffu, a1, o);
        a2 += __shfl_down_sync(0xffffffffu, a2, o);
    }
    if (lane == 0) {
        g_P[(size_t)row*3 + 0] = a0 + b4[0];
        g_P[(size_t)row*3 + 1] = a1 + b4[1];
        g_P[(size_t)row*3 + 2] = a2 + b4[2];
    }
}

// ================= ensemble + bilinear border skip =================
__global__ void ensemble(const float* __restrict__ coord, const float* __restrict__ inp,
                         float* __restrict__ out)
{
    int bq = blockIdx.x*256 + threadIdx.x;
    if (bq >= BB*QQ) return;
    int b = bq >> 14;
    float cy = coord[(size_t)bq*2 + 0];
    float cx = coord[(size_t)bq*2 + 1];
    int base = bq*4;
    float a0 = g_area[base+0], a1 = g_area[base+1], a2 = g_area[base+2], a3 = g_area[base+3];
    float inv = 1.0f/(a0 + a1 + a2 + a3);
    float w0 = a3*inv, w1 = a2*inv, w2 = a1*inv, w3 = a0*inv;
    float r[3];
    #pragma unroll
    for (int c = 0; c < 3; c++) {
        r[c] = g_P[(size_t)(base+0)*3 + c]*w0
             + g_P[(size_t)(base+1)*3 + c]*w1
             + g_P[(size_t)(base+2)*3 + c]*w2
             + g_P[(size_t)(base+3)*3 + c]*w3;
    }
    float fy = fminf(fmaxf((cy + 1.f)*24.f - 0.5f, 0.f), 47.f);
    float fx = fminf(fmaxf((cx + 1.f)*24.f - 0.5f, 0.f), 47.f);
    float y0f = floorf(fy), x0f = floorf(fx);
    int y0 = (int)y0f, x0 = (int)x0f;
    float wy = fy - y0f, wx = fx - x0f;
    int y1 = min(y0 + 1, 47), x1 = min(x0 + 1, 47);
    const float* ib = inp + (size_t)b*3*H0*W0;
    #pragma unroll
    for (int ch = 0; ch < 3; ch++) {
        const float* p = ib + ch*H0*W0;
        float v00 = p[y0*48 + x0], v01 = p[y0*48 + x1];
        float v10 = p[y1*48 + x0], v11 = p[y1*48 + x1];
        r[ch] += v00*(1.f - wy)*(1.f - wx) + v01*(1.f - wy)*wx
               + v10*wy*(1.f - wx) + v11*wy*wx;
        out[(size_t)bq*3 + ch] = r[ch];
    }
}

// ================= host launch =================
extern "C" void kernel_launch(void* const* d_in, const int* in_sizes, int n_in,
                              void* d_out, int out_size)
{
    const float* inp     = (const float*)d_in[0];
    const float* coord   = (const float*)d_in[1];
    const float* cell    = (const float*)d_in[2];
    const float* enc_w   = (const float*)d_in[3];
    const float* enc_b   = (const float*)d_in[4];
    const float* up1_w   = (const float*)d_in[5];
    const float* up1_b   = (const float*)d_in[6];
    const float* up2_w   = (const float*)d_in[7];
    const float* up2_b   = (const float*)d_in[8];
    const float* up3_w   = (const float*)d_in[9];
    const float* up3_b   = (const float*)d_in[10];
    const float* skip1_w = (const float*)d_in[11];
    const float* skip1_b = (const float*)d_in[12];
    const float* skip2_w = (const float*)d_in[13];
    const float* skip2_b = (const float*)d_in[14];
    const float* down4_w = (const float*)d_in[15];
    const float* down4_b = (const float*)d_in[16];
    const float* down5_w = (const float*)d_in[17];
    const float* down5_b = (const float*)d_in[18];
    const float* mlp_w0  = (const float*)d_in[19];
    const float* mlp_b0  = (const float*)d_in[20];
    const float* mlp_w1  = (const float*)d_in[21];
    const float* mlp_b1  = (const float*)d_in[22];
    const float* mlp_w2  = (const float*)d_in[23];
    const float* mlp_b2  = (const float*)d_in[24];
    const float* mlp_w3  = (const float*)d_in[25];
    const float* mlp_b3  = (const float*)d_in[26];
    const float* mlp_w4  = (const float*)d_in[27];
    const float* mlp_b4  = (const float*)d_in[28];
    float* out = (float*)d_out;

    float *p_feat, *p_feat1, *p_feat2, *p_feat3, *p_feat4, *p_feat5;
    __nv_bfloat16 *p_Xhi, *p_Xlo, *p_HAhi, *p_HAlo, *p_HBhi, *p_HBlo, *p_Whi, *p_Wlo;
    cudaGetSymbolAddress((void**)&p_feat,  g_feat);
    cudaGetSymbolAddress((void**)&p_feat1, g_feat1);
    cudaGetSymbolAddress((void**)&p_feat2, g_feat2);
    cudaGetSymbolAddress((void**)&p_feat3, g_feat3);
    cudaGetSymbolAddress((void**)&p_feat4, g_feat4);
    cudaGetSymbolAddress((void**)&p_feat5, g_feat5);
    cudaGetSymbolAddress((void**)&p_Xhi,  g_Xhi);
    cudaGetSymbolAddress((void**)&p_Xlo,  g_Xlo);
    cudaGetSymbolAddress((void**)&p_HAhi, g_HAhi);
    cudaGetSymbolAddress((void**)&p_HAlo, g_HAlo);
    cudaGetSymbolAddress((void**)&p_HBhi, g_HBhi);
    cudaGetSymbolAddress((void**)&p_HBlo, g_HBlo);
    cudaGetSymbolAddress((void**)&p_Whi,  g_Wthi);
    cudaGetSymbolAddress((void**)&p_Wlo,  g_Wtlo);

    // weight prep (independent of convs)
    {
        int total = 256*K0PAD + 3*256*256;
        prep_w<<<(total + 255)/256, 256>>>(mlp_w0, mlp_w1, mlp_w2, mlp_w3);
    }
    // encoder + pyramid
    {
        int total = BB*CC*H0*W0;
        enc_conv<<<(total + 255)/256, 256>>>(inp, enc_w, enc_b);
        dim3 blk(16,16);
        up_conv_ps<<<dim3(3,  3,  BB*64), blk>>>(p_feat,  p_feat1, 48, 48,  up1_w, up1_b);
        up_conv_ps<<<dim3(6,  6,  BB*64), blk>>>(p_feat1, p_feat2, 96, 96,  up2_w, up2_b);
        up_conv_ps<<<dim3(12, 12, BB*64), blk>>>(p_feat2, p_feat3, 192,192, up3_w, up3_b);
        down_fused<<<dim3(12, 12, BB*16), blk>>>(p_feat3, p_feat2, p_feat4, 192, 192,
                                                 down4_w, down4_b, skip1_w, skip1_b);
        down_fused<<<dim3(6,  6,  BB*16), blk>>>(p_feat4, p_feat1, p_feat5, 96, 96,
                                                 down5_w, down5_b, skip2_w, skip2_b);
    }
    // gather + build X (bf16 hi/lo)
    gather_build<<<MROWS/4, 256>>>(coord, cell);

    // MLP hidden layers on mma.sync tensor cores
    {
        dim3 grid(MROWS/128, 2);
        const __nv_bfloat16* W1hi = p_Whi + 256*K0PAD;
        const __nv_bfloat16* W1lo = p_Wlo + 256*K0PAD;
        const __nv_bfloat16* W2hi = W1hi + 65536;
        const __nv_bfloat16* W2lo = W1lo + 65536;
        const __nv_bfloat16* W3hi = W2hi + 65536;
        const __nv_bfloat16* W3lo = W2lo + 65536;
        mlp_gemm_mma<<<grid, 256>>>(p_Xhi,  p_Xlo,  K0PAD, p_Whi, p_Wlo, mlp_b0, p_HAhi, p_HAlo);
        mlp_gemm_mma<<<grid, 256>>>(p_HAhi, p_HAlo, 256,   W1hi,  W1lo,  mlp_b1, p_HBhi, p_HBlo);
        mlp_gemm_mma<<<grid, 256>>>(p_HBhi, p_HBlo, 256,   W2hi,  W2lo,  mlp_b2, p_HAhi, p_HAlo);
        mlp_gemm_mma<<<grid, 256>>>(p_HAhi, p_HAlo, 256,   W3hi,  W3lo,  mlp_b3, p_HBhi, p_HBlo);
    }
    // last layer + ensemble
    mlp_last<<<MROWS/4, 128>>>(p_HBhi, p_HBlo, mlp_w4, mlp_b4);
    ensemble<<<(BB*QQ + 255)/256, 256>>>(coord, inp, out);
}